// round 1
// baseline (speedup 1.0000x reference)
#include <cuda_runtime.h>
#include <cuda_bf16.h>
#include <math.h>

// Problem constants
#define B   8
#define T   16
#define CIN 3
#define HID 64
#define HW  64
#define PIX (HW*HW)          // 4096

#define KC 16                // input-channel chunk held in smem

// ---------------- scratch (no allocation allowed) ----------------
__device__ float g_xin[B*T*CIN*PIX];          // attention-scaled input
__device__ float g_h0[2][B*HID*PIX];          // layer0 hidden, double buffered
__device__ float g_c0[B*HID*PIX];             // layer0 cell (in-place per elem)
__device__ float g_h1[2][B*HID*PIX];          // layer1 hidden, double buffered
__device__ float g_c1[B*HID*PIX];             // layer1 cell

// ---------------- attention + input scaling ----------------
// one block per (b,t); computes per-channel mean & max over HxW, the tiny
// SE MLP, then writes xin = x * sigmoid(...)
__global__ void attention_kernel(const float* __restrict__ x,
                                 const float* __restrict__ w1,
                                 const float* __restrict__ w2,
                                 float* __restrict__ xin)
{
    const int bt = blockIdx.x;                 // 0..127
    const float* xp = x  + (long)bt * CIN * PIX;
    float*       xo = xin + (long)bt * CIN * PIX;

    __shared__ float s_sum[256], s_max[256];
    __shared__ float chAvg[CIN], chMax[CIN], scale[CIN];

    for (int c = 0; c < CIN; ++c) {
        float s = 0.f, m = -INFINITY;
        for (int i = threadIdx.x; i < PIX; i += 256) {
            float v = xp[c*PIX + i];
            s += v; m = fmaxf(m, v);
        }
        s_sum[threadIdx.x] = s; s_max[threadIdx.x] = m;
        __syncthreads();
        for (int off = 128; off > 0; off >>= 1) {
            if (threadIdx.x < off) {
                s_sum[threadIdx.x] += s_sum[threadIdx.x + off];
                s_max[threadIdx.x] = fmaxf(s_max[threadIdx.x], s_max[threadIdx.x + off]);
            }
            __syncthreads();
        }
        if (threadIdx.x == 0) { chAvg[c] = s_sum[0] / (float)PIX; chMax[c] = s_max[0]; }
        __syncthreads();
    }
    if (threadIdx.x == 0) {
        float ha = w1[0]*chAvg[0] + w1[1]*chAvg[1] + w1[2]*chAvg[2];
        float hm = w1[0]*chMax[0] + w1[1]*chMax[1] + w1[2]*chMax[2];
        ha = fmaxf(ha, 0.f); hm = fmaxf(hm, 0.f);
        float hs = ha + hm;
        for (int c = 0; c < CIN; ++c)
            scale[c] = 1.f / (1.f + expf(-w2[c]*hs));
    }
    __syncthreads();
    for (int c = 0; c < CIN; ++c)
        for (int i = threadIdx.x; i < PIX; i += 256)
            xo[c*PIX + i] = xp[c*PIX + i] * scale[c];
}

// ---------------- fused conv(3x3 SAME) + LSTM pointwise step ----------------
// grid: (16 row-tiles, 8 hidden-groups, 8 batches), 256 threads.
// Each warp owns one hidden channel j; lane handles cols {lane, lane+32}
// for 4 rows  -> 4 gates x 8 pixels = 32 fp32 accumulators.
__global__ __launch_bounds__(256)
void convlstm_step(const float* __restrict__ srcA, int CA, long sA,   // first Cin part
                   const float* __restrict__ srcB, long sB,           // hidden part
                   int Cin,
                   const float* __restrict__ W,                       // [4*HID, Cin, 3,3]
                   const float* __restrict__ bias,                    // [4*HID]
                   float* __restrict__ cState,                        // [B,HID,PIX] in/out
                   float* __restrict__ hOut,  long hOutStride,
                   float* __restrict__ hOut2, long hOut2Stride,       // optional (out1 slice)
                   float* __restrict__ hFin,  float* __restrict__ cFin)
{
    const int b    = blockIdx.z;
    const int warp = threadIdx.x >> 5;
    const int lane = threadIdx.x & 31;
    const int j    = blockIdx.y * 8 + warp;    // hidden channel
    const int r0   = blockIdx.x * 4;           // first output row

    __shared__ float in_s[KC*6*66];            // channels x (4+2 rows) x (64+2 cols)
    __shared__ float w_s[8*4*KC*9];            // [wj][gate][kc][9]

    float acc[4][4][2];
    #pragma unroll
    for (int g = 0; g < 4; ++g)
        #pragma unroll
        for (int r = 0; r < 4; ++r) { acc[g][r][0] = 0.f; acc[g][r][1] = 0.f; }

    const float* srcAb = srcA + (long)b * sA;
    const float* srcBb = srcB + (long)b * sB;

    for (int c0 = 0; c0 < Cin; c0 += KC) {
        const int kcCnt = min(KC, Cin - c0);
        __syncthreads();
        // ---- stage input tile (with halo + zero pad) ----
        const int total = kcCnt * 6 * 66;
        for (int idx = threadIdx.x; idx < total; idx += 256) {
            int col = idx % 66;
            int row = (idx / 66) % 6;
            int kc  = idx / (66*6);
            int c   = c0 + kc;
            int gr  = r0 + row - 1;
            int gc  = col - 1;
            float v = 0.f;
            if (gr >= 0 && gr < HW && gc >= 0 && gc < HW) {
                v = (c < CA) ? srcAb[(long)c      *PIX + gr*HW + gc]
                             : srcBb[(long)(c-CA) *PIX + gr*HW + gc];
            }
            in_s[idx] = v;
        }
        // ---- stage weights for this block's 8 hidden channels ----
        const int wtotal = 8 * 4 * kcCnt * 9;
        for (int idx = threadIdx.x; idx < wtotal; idx += 256) {
            int k9 = idx % 9;
            int kc = (idx / 9) % kcCnt;
            int g  = (idx / (9*kcCnt)) % 4;
            int wj = idx / (9*kcCnt*4);
            int oc = g*HID + blockIdx.y*8 + wj;
            w_s[((wj*4 + g)*KC + kc)*9 + k9] = W[((long)oc*Cin + c0 + kc)*9 + k9];
        }
        __syncthreads();

        // ---- accumulate ----
        for (int kc = 0; kc < kcCnt; ++kc) {
            #pragma unroll
            for (int ky = 0; ky < 3; ++ky) {
                #pragma unroll
                for (int kx = 0; kx < 3; ++kx) {
                    const int kk = ky*3 + kx;
                    float w0 = w_s[((warp*4+0)*KC + kc)*9 + kk];
                    float w1 = w_s[((warp*4+1)*KC + kc)*9 + kk];
                    float w2 = w_s[((warp*4+2)*KC + kc)*9 + kk];
                    float w3 = w_s[((warp*4+3)*KC + kc)*9 + kk];
                    #pragma unroll
                    for (int r = 0; r < 4; ++r) {
                        float a0 = in_s[(kc*6 + r + ky)*66 + lane + kx];
                        float a1 = in_s[(kc*6 + r + ky)*66 + lane + 32 + kx];
                        acc[0][r][0] += w0*a0;  acc[0][r][1] += w0*a1;
                        acc[1][r][0] += w1*a0;  acc[1][r][1] += w1*a1;
                        acc[2][r][0] += w2*a0;  acc[2][r][1] += w2*a1;
                        acc[3][r][0] += w3*a0;  acc[3][r][1] += w3*a1;
                    }
                }
            }
        }
    }

    // ---- fused LSTM pointwise update ----
    const float bi = bias[j], bf = bias[HID + j], bo = bias[2*HID + j], bg = bias[3*HID + j];
    const long cBase = ((long)b*HID + j)*PIX;
    #pragma unroll
    for (int r = 0; r < 4; ++r) {
        #pragma unroll
        for (int h2 = 0; h2 < 2; ++h2) {
            const int  pix = (r0 + r)*HW + lane + h2*32;
            const long cOff = cBase + pix;
            float ig = 1.f/(1.f + __expf(-(acc[0][r][h2] + bi)));
            float fg = 1.f/(1.f + __expf(-(acc[1][r][h2] + bf)));
            float og = 1.f/(1.f + __expf(-(acc[2][r][h2] + bo)));
            float gg = tanhf(acc[3][r][h2] + bg);
            float cNew = fg * cState[cOff] + ig * gg;
            float hNew = og * tanhf(cNew);
            cState[cOff] = cNew;
            hOut[(long)b*hOutStride + (long)j*PIX + pix] = hNew;
            if (hOut2) hOut2[(long)b*hOut2Stride + (long)j*PIX + pix] = hNew;
            if (hFin)  hFin[cBase + pix] = hNew;
            if (cFin)  cFin[cBase + pix] = cNew;
        }
    }
}

// ---------------- host ----------------
extern "C" void kernel_launch(void* const* d_in, const int* in_sizes, int n_in,
                              void* d_out, int out_size)
{
    const float* x       = (const float*)d_in[0];
    const float* att_w1  = (const float*)d_in[1];
    const float* att_w2  = (const float*)d_in[2];
    const float* conv_w0 = (const float*)d_in[3];
    const float* conv_b0 = (const float*)d_in[4];
    const float* conv_w1 = (const float*)d_in[5];
    const float* conv_b1 = (const float*)d_in[6];
    float* out = (float*)d_out;

    float *xin, *h0_0, *h0_1, *c0, *h1_0, *h1_1, *c1;
    cudaGetSymbolAddress((void**)&xin,  g_xin);
    cudaGetSymbolAddress((void**)&h0_0, g_h0);   h0_1 = h0_0 + (long)B*HID*PIX;
    cudaGetSymbolAddress((void**)&c0,   g_c0);
    cudaGetSymbolAddress((void**)&h1_0, g_h1);   h1_1 = h1_0 + (long)B*HID*PIX;
    cudaGetSymbolAddress((void**)&c1,   g_c1);

    const size_t stBytes = (size_t)B*HID*PIX*sizeof(float);
    cudaMemsetAsync(h0_0, 0, stBytes);
    cudaMemsetAsync(c0,   0, stBytes);
    cudaMemsetAsync(h1_0, 0, stBytes);
    cudaMemsetAsync(c1,   0, stBytes);

    attention_kernel<<<B*T, 256>>>(x, att_w1, att_w2, xin);

    float* h0buf[2] = {h0_0, h0_1};
    float* h1buf[2] = {h1_0, h1_1};

    float* out1  = out;                                  // [B,T,HID,PIX]
    float* h1fin = out + (long)B*T*HID*PIX;              // [B,HID,PIX]
    float* c1fin = h1fin + (long)B*HID*PIX;              // [B,HID,PIX]

    dim3 grid(HW/4, HID/8, B);

    for (int t = 0; t < T; ++t) {
        const int p = t & 1;
        // layer 0: in = [xin(t) (3ch) | h0], out -> h0(other parity), c0 in-place
        convlstm_step<<<grid, 256>>>(
            xin + (long)t*CIN*PIX, CIN, (long)T*CIN*PIX,
            h0buf[p], (long)HID*PIX,
            CIN + HID, conv_w0, conv_b0,
            c0,
            h0buf[p^1], (long)HID*PIX,
            nullptr, 0, nullptr, nullptr);
        // layer 1: in = [h0_new (64ch) | h1], out -> h1(other parity) + out1[:,t]
        convlstm_step<<<grid, 256>>>(
            h0buf[p^1], HID, (long)HID*PIX,
            h1buf[p], (long)HID*PIX,
            2*HID, conv_w1, conv_b1,
            c1,
            h1buf[p^1], (long)HID*PIX,
            out1 + (long)t*HID*PIX, (long)T*HID*PIX,
            (t == T-1) ? h1fin : nullptr,
            (t == T-1) ? c1fin : nullptr);
    }
}